// round 9
// baseline (speedup 1.0000x reference)
#include <cuda_runtime.h>
#include <cuda_fp16.h>
#include <cstdint>

#define N_NODES 8192
#define IN_F    512
#define OUT_F   128
#define SPLITJ  2
#define NCHUNK  ((N_NODES / SPLITJ) / 64)   // 64
#define LOG2E   1.44269504f

// ---------------- scratch (device globals: no allocation allowed) -------------
__device__ float  g_h[(size_t)N_NODES * OUT_F];                // 4 MB
__device__ float  g_p[N_NODES];
__device__ float  g_q[N_NODES];
__device__ __half g_hT[(size_t)OUT_F * N_NODES];               // 2 MB  h^T fp16
__device__ float  g_acc[(size_t)SPLITJ * N_NODES * OUT_F];     // 8 MB
__device__ float  g_den[SPLITJ * N_NODES];

// ============================ helpers =========================================
__device__ __forceinline__ uint32_t smem_u32_of(const void* p) {
    uint32_t a;
    asm("{ .reg .u64 t; cvta.to.shared.u64 t, %1; cvt.u32.u64 %0, t; }"
        : "=r"(a) : "l"(p));
    return a;
}
__device__ __forceinline__ float ex2f(float x) {
    float r; asm("ex2.approx.f32 %0, %1;" : "=f"(r) : "f"(x)); return r;
}
__device__ __forceinline__ uint32_t pack_f16x2(float lo, float hi) {
    uint32_t r; asm("cvt.rn.f16x2.f32 %0, %1, %2;" : "=r"(r) : "f"(hi), "f"(lo));
    return r;
}
__device__ __forceinline__ void sts128(uint32_t a, uint4 v) {
    asm volatile("st.shared.v4.b32 [%0], {%1,%2,%3,%4};"
                 :: "r"(a), "r"(v.x), "r"(v.y), "r"(v.z), "r"(v.w));
}
#define LDSM4(R, ADDR) \
    asm volatile("ldmatrix.sync.aligned.m8n8.x4.shared.b16 {%0,%1,%2,%3}, [%4];" \
                 : "=r"((R)[0]), "=r"((R)[1]), "=r"((R)[2]), "=r"((R)[3])        \
                 : "r"(ADDR))
#define MMA(C, A, B0, B1) \
    asm volatile("mma.sync.aligned.m16n8k16.row.col.f32.f16.f16.f32 "            \
                 "{%0,%1,%2,%3}, {%4,%5,%6,%7}, {%8,%9}, {%0,%1,%2,%3};"         \
                 : "+f"((C)[0]), "+f"((C)[1]), "+f"((C)[2]), "+f"((C)[3])        \
                 : "r"((A)[0]), "r"((A)[1]), "r"((A)[2]), "r"((A)[3]),           \
                   "r"(B0), "r"(B1))

// w = exp(sigmoid(p_i+q_j)) = exp(1/(1+a*b)); deg-4 poly for e^s on [0,1]
__device__ __forceinline__ float wpoly(float a, float b, int m) {
    float c = fmaf(a, b, 1.0f);
    float s; asm("rcp.approx.f32 %0, %1;" : "=f"(s) : "f"(c));
    float p = fmaf(0.069558f, s, 0.139972f);
    p = fmaf(p, s, 0.510039f);
    p = fmaf(p, s, 0.998663f);
    p = fmaf(p, s, 1.000035f);
    return (m != 0) ? p : 0.0f;
}

// ======================= Kernel A: h = X @ W (fp32) ===========================
__global__ void __launch_bounds__(256) gemm_xw_kernel(const float* __restrict__ X,
                                                      const float* __restrict__ W) {
    __shared__ float Xs[16][64];
    __shared__ float Ws[16][128];
    const int tid = threadIdx.x;
    const int rg  = tid >> 5;
    const int cg  = tid & 31;
    const int row0 = blockIdx.x * 64;

    float acc[8][4];
#pragma unroll
    for (int r = 0; r < 8; r++)
#pragma unroll
        for (int c = 0; c < 4; c++) acc[r][c] = 0.f;

    for (int k0 = 0; k0 < IN_F; k0 += 16) {
        {
            int r  = tid >> 2;
            int kq = (tid & 3) << 2;
            float4 v = *(const float4*)&X[(size_t)(row0 + r) * IN_F + k0 + kq];
            Xs[kq + 0][r] = v.x;  Xs[kq + 1][r] = v.y;
            Xs[kq + 2][r] = v.z;  Xs[kq + 3][r] = v.w;
        }
#pragma unroll
        for (int u = 0; u < 2; u++) {
            int e  = tid + u * 256;
            int kr = e >> 5;
            int cc = (e & 31) << 2;
            *(float4*)&Ws[kr][cc] = *(const float4*)&W[(size_t)(k0 + kr) * OUT_F + cc];
        }
        __syncthreads();
#pragma unroll
        for (int kk = 0; kk < 16; kk++) {
            float4 b = *(const float4*)&Ws[kk][cg << 2];
            float a8[8];
            *(float4*)&a8[0] = *(const float4*)&Xs[kk][rg * 8];
            *(float4*)&a8[4] = *(const float4*)&Xs[kk][rg * 8 + 4];
#pragma unroll
            for (int r = 0; r < 8; r++) {
                acc[r][0] += a8[r] * b.x;  acc[r][1] += a8[r] * b.y;
                acc[r][2] += a8[r] * b.z;  acc[r][3] += a8[r] * b.w;
            }
        }
        __syncthreads();
    }
#pragma unroll
    for (int r = 0; r < 8; r++) {
        int row = row0 + rg * 8 + r;
        *(float4*)&g_h[(size_t)row * OUT_F + (cg << 2)] =
            make_float4(acc[r][0], acc[r][1], acc[r][2], acc[r][3]);
    }
}

// ======================= Kernel B: p = h@a1, q = h@a2 =========================
__global__ void __launch_bounds__(256) pq_kernel(const float* __restrict__ a1,
                                                 const float* __restrict__ a2) {
    int gwarp = (blockIdx.x * blockDim.x + threadIdx.x) >> 5;
    int lane  = threadIdx.x & 31;
    if (gwarp >= N_NODES) return;
    float4 hv  = *(const float4*)&g_h[(size_t)gwarp * OUT_F + (lane << 2)];
    float4 av1 = *(const float4*)&a1[lane << 2];
    float4 av2 = *(const float4*)&a2[lane << 2];
    float s1 = hv.x * av1.x + hv.y * av1.y + hv.z * av1.z + hv.w * av1.w;
    float s2 = hv.x * av2.x + hv.y * av2.y + hv.z * av2.z + hv.w * av2.w;
#pragma unroll
    for (int o = 16; o; o >>= 1) {
        s1 += __shfl_xor_sync(0xffffffffu, s1, o);
        s2 += __shfl_xor_sync(0xffffffffu, s2, o);
    }
    if (lane == 0) { g_p[gwarp] = s1; g_q[gwarp] = s2; }
}

// ============ Kernel T: h -> h^T fp16 (transpose) =============================
__device__ __forceinline__ uint32_t pk2(__half a, __half b) {
    return (uint32_t)__half_as_ushort(a) | ((uint32_t)__half_as_ushort(b) << 16);
}
__global__ void __launch_bounds__(256) trans_kernel() {
    __shared__ float hs[32][132];
    const int tid = threadIdx.x;
    const int j0  = blockIdx.x * 32;
#pragma unroll
    for (int u = 0; u < 4; ++u) {
        int e = tid + u * 256;
        int r = e >> 5, c4 = (e & 31) << 2;
        *(float4*)&hs[r][c4] = *(const float4*)&g_h[(size_t)(j0 + r) * OUT_F + c4];
    }
    __syncthreads();
    const int f = tid >> 1, half = tid & 1;
    uint32_t hi8[8];
#pragma unroll
    for (int k = 0; k < 8; ++k) {
        float v0 = hs[half * 16 + 2 * k][f];
        float v1 = hs[half * 16 + 2 * k + 1][f];
        hi8[k] = pk2(__float2half_rn(v0), __float2half_rn(v1));
    }
    size_t ob = ((size_t)f * N_NODES + j0 + half * 16) * 2;
    *(uint4*)((char*)g_hT + ob)      = make_uint4(hi8[0], hi8[1], hi8[2], hi8[3]);
    *(uint4*)((char*)g_hT + ob + 16) = make_uint4(hi8[4], hi8[5], hi8[6], hi8[7]);
}

// ======================= Kernel C: warp-specialized fused attention ===========
// grid (64, SPLITJ), 384 thr. Warps 0-3 = producers (weights + staging),
// warps 4-11 = consumers (mma.sync, each 32 i x 64 cols). Double-buffered.
// buf: A = w fp16 [128][72h] (18432 B) | B = h^T fp16 [128 f][72h] (18432 B)
#define ABASE(b) ((uint32_t)(b) * 36864u)
#define BBASE(b) ((uint32_t)(b) * 36864u + 18432u)
#define SMEM_ATTN 73728u

// producer staging of chunk cc into buffer bo (tid 0..127)
#define STAGE(cc, bo) do {                                                       \
    const int jc = jstart + (cc) * 64 + jo;                                      \
    float4 q0 = *(const float4*)(g_q + jc);                                      \
    float4 q1 = *(const float4*)(g_q + jc + 4);                                  \
    float bv0 = ex2f(-q0.x * LOG2E), bv1 = ex2f(-q0.y * LOG2E);                  \
    float bv2 = ex2f(-q0.z * LOG2E), bv3 = ex2f(-q0.w * LOG2E);                  \
    float bv4 = ex2f(-q1.x * LOG2E), bv5 = ex2f(-q1.y * LOG2E);                  \
    float bv6 = ex2f(-q1.z * LOG2E), bv7 = ex2f(-q1.w * LOG2E);                  \
    _Pragma("unroll")                                                            \
    for (int v = 0; v < 8; ++v) {                                                \
        int f = rbase + 16 * v;                                                  \
        uint4 hv = *(const uint4*)(g_hT + (size_t)f * N_NODES + jc);             \
        sts128(sb + BBASE(bo) + (uint32_t)(f * 144 + jo * 2), hv);               \
    }                                                                            \
    _Pragma("unroll")                                                            \
    for (int u = 0; u < 8; ++u) {                                                \
        const int* ap = adjb + (size_t)(16 * u) * N_NODES + (cc) * 64;           \
        int4 m0 = *(const int4*)ap;                                              \
        int4 m1 = *(const int4*)(ap + 4);                                        \
        float w0 = wpoly(a8[u], bv0, m0.x), w1 = wpoly(a8[u], bv1, m0.y);        \
        float w2 = wpoly(a8[u], bv2, m0.z), w3 = wpoly(a8[u], bv3, m0.w);        \
        float w4 = wpoly(a8[u], bv4, m1.x), w5 = wpoly(a8[u], bv5, m1.y);        \
        float w6 = wpoly(a8[u], bv6, m1.z), w7 = wpoly(a8[u], bv7, m1.w);        \
        dsum[u] += ((w0 + w1) + (w2 + w3)) + ((w4 + w5) + (w6 + w7));            \
        uint4 pw = make_uint4(pack_f16x2(w0, w1), pack_f16x2(w2, w3),            \
                              pack_f16x2(w4, w5), pack_f16x2(w6, w7));           \
        sts128(sb + ABASE(bo) + (uint32_t)((rbase + 16 * u) * 144 + jo * 2), pw);\
    }                                                                            \
} while (0)

__global__ void __launch_bounds__(384, 1) attn_kernel(const int* __restrict__ adj) {
    extern __shared__ __align__(16) char smem[];
    const uint32_t sb = smem_u32_of(smem);
    const int tid  = threadIdx.x;
    const int lane = tid & 31;
    const int wid  = tid >> 5;
    const int i0     = blockIdx.x * 128;
    const int jstart = blockIdx.y * (N_NODES / SPLITJ);

    // ---------- producer state (warps 0-3; tid 0..127) ----------
    const int rbase = tid >> 3;          // 0..15 (row group)
    const int jo    = (tid & 7) * 8;     // j offset 0..56
    const int* adjb = adj + (size_t)(i0 + rbase) * N_NODES + jstart + jo;
    float a8[8], dsum[8];

    // ---------- consumer state (warps 4-11) ----------
    float acc[2][8][4];                  // 32 i x 64 cols -> 64 regs
    const int cw  = wid - 4;             // 0..7
    const int iw0 = (cw & 3) * 32;       // i sub-tile
    const int nw0 = (cw >> 2) * 64;      // col sub-tile
    const uint32_t aThb = (uint32_t)((iw0 + (lane & 15)) * 144 + 16 * (lane >> 4));
    const uint32_t bThb = (uint32_t)(((nw0 + (lane & 7) + 8 * ((lane >> 4) & 1)) * 144) +
                                     16 * ((lane >> 3) & 1));

    if (wid < 4) {
#pragma unroll
        for (int u = 0; u < 8; ++u) {
            a8[u]   = ex2f(-g_p[i0 + rbase + 16 * u] * LOG2E);
            dsum[u] = 0.f;
        }
        STAGE(0, 0);
    } else {
#pragma unroll
        for (int mt = 0; mt < 2; ++mt)
#pragma unroll
            for (int nt = 0; nt < 8; ++nt)
#pragma unroll
                for (int k = 0; k < 4; ++k) acc[mt][nt][k] = 0.f;
    }
    __syncthreads();

    for (int c = 0; c < NCHUNK; ++c) {
        if (wid < 4) {
            if (c + 1 < NCHUNK) STAGE(c + 1, (c + 1) & 1);
        } else if (wid < 12) {
            const uint32_t ab = sb + ABASE(c & 1) + aThb;
            const uint32_t bb = sb + BBASE(c & 1) + bThb;
#pragma unroll
            for (int ks = 0; ks < 4; ++ks) {
                uint32_t A0[4], A1[4];
                LDSM4(A0, ab + ks * 32);
                LDSM4(A1, ab + 2304 + ks * 32);
#pragma unroll
                for (int nt2 = 0; nt2 < 4; ++nt2) {
                    uint32_t B[4];
                    LDSM4(B, bb + nt2 * 2304 + ks * 32);
                    MMA(acc[0][2 * nt2],     A0, B[0], B[1]);
                    MMA(acc[0][2 * nt2 + 1], A0, B[2], B[3]);
                    MMA(acc[1][2 * nt2],     A1, B[0], B[1]);
                    MMA(acc[1][2 * nt2 + 1], A1, B[2], B[3]);
                }
            }
        }
        __syncthreads();
    }

    if (wid < 4) {
        // denominators: 8 lanes (same row) hold partial sums over j
#pragma unroll
        for (int u = 0; u < 8; ++u) {
            float v = dsum[u];
            v += __shfl_xor_sync(0xffffffffu, v, 1);
            v += __shfl_xor_sync(0xffffffffu, v, 2);
            v += __shfl_xor_sync(0xffffffffu, v, 4);
            if ((lane & 7) == 0)
                g_den[blockIdx.y * N_NODES + i0 + rbase + 16 * u] = v;
        }
    } else {
        // write partial numerators from mma fragments
        const int r0 = lane >> 2;
        const int cp = (lane & 3) * 2;
#pragma unroll
        for (int mt = 0; mt < 2; ++mt)
#pragma unroll
            for (int nt = 0; nt < 8; ++nt) {
                int row = i0 + iw0 + 16 * mt + r0;
                int col = nw0 + 8 * nt + cp;
                size_t base = ((size_t)blockIdx.y * N_NODES + row) * OUT_F + col;
                *(float2*)&g_acc[base] = make_float2(acc[mt][nt][0], acc[mt][nt][1]);
                *(float2*)&g_acc[base + 8 * OUT_F] =
                    make_float2(acc[mt][nt][2], acc[mt][nt][3]);
            }
    }
}

// ======================= Kernel D: combine splits =============================
__global__ void __launch_bounds__(256) combine_kernel(float* __restrict__ out) {
    int e = blockIdx.x * blockDim.x + threadIdx.x;
    int i = e >> 5;
    int c = (e & 31) << 2;
    float4 s = make_float4(0.f, 0.f, 0.f, 0.f);
    float d = 0.f;
#pragma unroll
    for (int sp = 0; sp < SPLITJ; sp++) {
        float4 a = *(const float4*)&g_acc[((size_t)sp * N_NODES + i) * OUT_F + c];
        s.x += a.x; s.y += a.y; s.z += a.z; s.w += a.w;
        d += g_den[sp * N_NODES + i];
    }
    float inv = __fdividef(1.f, d);
    *(float4*)&out[(size_t)i * OUT_F + c] =
        make_float4(s.x * inv, s.y * inv, s.z * inv, s.w * inv);
}

// =============================================================================
extern "C" void kernel_launch(void* const* d_in, const int* in_sizes, int n_in,
                              void* d_out, int out_size) {
    const float* X   = (const float*)d_in[0];
    const int*   adj = (const int*)d_in[1];
    const float* W   = (const float*)d_in[2];
    const float* a1  = (const float*)d_in[3];
    const float* a2  = (const float*)d_in[4];
    float* out = (float*)d_out;

    cudaFuncSetAttribute(attn_kernel, cudaFuncAttributeMaxDynamicSharedMemorySize,
                         SMEM_ATTN);

    gemm_xw_kernel<<<N_NODES / 64, 256>>>(X, W);
    pq_kernel<<<N_NODES / 8, 256>>>(a1, a2);
    trans_kernel<<<N_NODES / 32, 256>>>();
    attn_kernel<<<dim3(N_NODES / 128, SPLITJ), 384, SMEM_ATTN>>>(adj);
    combine_kernel<<<(N_NODES * 32) / 256, 256>>>(out);
}

// round 11
// speedup vs baseline: 1.5152x; 1.5152x over previous
#include <cuda_runtime.h>
#include <cuda_fp16.h>
#include <cstdint>

#define N_NODES 8192
#define IN_F    512
#define OUT_F   128
#define SPLITJ  2
#define NCHUNK  ((N_NODES / SPLITJ) / 64)   // 64
#define LOG2E   1.44269504f

// ---------------- scratch (device globals: no allocation allowed) -------------
__device__ float  g_h[(size_t)N_NODES * OUT_F];                // 4 MB
__device__ float  g_p[N_NODES];
__device__ float  g_q[N_NODES];
__device__ __half g_hT[(size_t)OUT_F * N_NODES];               // 2 MB  h^T fp16
__device__ float  g_acc[(size_t)SPLITJ * N_NODES * OUT_F];     // 8 MB
__device__ float  g_den[SPLITJ * N_NODES];

// ============================ helpers =========================================
__device__ __forceinline__ uint32_t smem_u32_of(const void* p) {
    uint32_t a;
    asm("{ .reg .u64 t; cvta.to.shared.u64 t, %1; cvt.u32.u64 %0, t; }"
        : "=r"(a) : "l"(p));
    return a;
}
__device__ __forceinline__ float ex2f(float x) {
    float r; asm("ex2.approx.f32 %0, %1;" : "=f"(r) : "f"(x)); return r;
}
__device__ __forceinline__ uint32_t pack_f16x2(float lo, float hi) {
    uint32_t r; asm("cvt.rn.f16x2.f32 %0, %1, %2;" : "=r"(r) : "f"(hi), "f"(lo));
    return r;
}
__device__ __forceinline__ void sts128(uint32_t a, uint4 v) {
    asm volatile("st.shared.v4.b32 [%0], {%1,%2,%3,%4};"
                 :: "r"(a), "r"(v.x), "r"(v.y), "r"(v.z), "r"(v.w));
}
__device__ __forceinline__ float4 lds128f(uint32_t a) {
    float4 v;
    asm volatile("ld.shared.v4.f32 {%0,%1,%2,%3}, [%4];"
                 : "=f"(v.x), "=f"(v.y), "=f"(v.z), "=f"(v.w) : "r"(a));
    return v;
}
__device__ __forceinline__ int4 lds128i(uint32_t a) {
    int4 v;
    asm volatile("ld.shared.v4.b32 {%0,%1,%2,%3}, [%4];"
                 : "=r"(v.x), "=r"(v.y), "=r"(v.z), "=r"(v.w) : "r"(a));
    return v;
}
__device__ __forceinline__ void stsf(uint32_t a, float v) {
    asm volatile("st.shared.f32 [%0], %1;" :: "r"(a), "f"(v));
}
#define CPA16(dst, src) \
    asm volatile("cp.async.cg.shared.global [%0], [%1], 16;" \
                 :: "r"(dst), "l"(src) : "memory")
#define CPA_COMMIT() asm volatile("cp.async.commit_group;" ::: "memory")
#define CPA_WAIT1()  asm volatile("cp.async.wait_group 1;" ::: "memory")
#define CPA_WAIT0()  asm volatile("cp.async.wait_group 0;" ::: "memory")

#define LDSM4(R, ADDR) \
    asm volatile("ldmatrix.sync.aligned.m8n8.x4.shared.b16 {%0,%1,%2,%3}, [%4];" \
                 : "=r"((R)[0]), "=r"((R)[1]), "=r"((R)[2]), "=r"((R)[3])        \
                 : "r"(ADDR))
#define MMA(C, A, B0, B1) \
    asm volatile("mma.sync.aligned.m16n8k16.row.col.f32.f16.f16.f32 "            \
                 "{%0,%1,%2,%3}, {%4,%5,%6,%7}, {%8,%9}, {%0,%1,%2,%3};"         \
                 : "+f"((C)[0]), "+f"((C)[1]), "+f"((C)[2]), "+f"((C)[3])        \
                 : "r"((A)[0]), "r"((A)[1]), "r"((A)[2]), "r"((A)[3]),           \
                   "r"(B0), "r"(B1))

// w = exp(sigmoid(p_i+q_j)) = exp(1/(1+a*b)); deg-4 poly for e^s on [0,1]
__device__ __forceinline__ float wpoly(float a, float b, int m) {
    float c = fmaf(a, b, 1.0f);
    float s; asm("rcp.approx.f32 %0, %1;" : "=f"(s) : "f"(c));
    float p = fmaf(0.069558f, s, 0.139972f);
    p = fmaf(p, s, 0.510039f);
    p = fmaf(p, s, 0.998663f);
    p = fmaf(p, s, 1.000035f);
    return (m != 0) ? p : 0.0f;
}

// ======================= Kernel A: h = X @ W (fp32) ===========================
__global__ void __launch_bounds__(256) gemm_xw_kernel(const float* __restrict__ X,
                                                      const float* __restrict__ W) {
    __shared__ float Xs[16][64];
    __shared__ float Ws[16][128];
    const int tid = threadIdx.x;
    const int rg  = tid >> 5;
    const int cg  = tid & 31;
    const int row0 = blockIdx.x * 64;

    float acc[8][4];
#pragma unroll
    for (int r = 0; r < 8; r++)
#pragma unroll
        for (int c = 0; c < 4; c++) acc[r][c] = 0.f;

    for (int k0 = 0; k0 < IN_F; k0 += 16) {
        {
            int r  = tid >> 2;
            int kq = (tid & 3) << 2;
            float4 v = *(const float4*)&X[(size_t)(row0 + r) * IN_F + k0 + kq];
            Xs[kq + 0][r] = v.x;  Xs[kq + 1][r] = v.y;
            Xs[kq + 2][r] = v.z;  Xs[kq + 3][r] = v.w;
        }
#pragma unroll
        for (int u = 0; u < 2; u++) {
            int e  = tid + u * 256;
            int kr = e >> 5;
            int cc = (e & 31) << 2;
            *(float4*)&Ws[kr][cc] = *(const float4*)&W[(size_t)(k0 + kr) * OUT_F + cc];
        }
        __syncthreads();
#pragma unroll
        for (int kk = 0; kk < 16; kk++) {
            float4 b = *(const float4*)&Ws[kk][cg << 2];
            float a8[8];
            *(float4*)&a8[0] = *(const float4*)&Xs[kk][rg * 8];
            *(float4*)&a8[4] = *(const float4*)&Xs[kk][rg * 8 + 4];
#pragma unroll
            for (int r = 0; r < 8; r++) {
                acc[r][0] += a8[r] * b.x;  acc[r][1] += a8[r] * b.y;
                acc[r][2] += a8[r] * b.z;  acc[r][3] += a8[r] * b.w;
            }
        }
        __syncthreads();
    }
#pragma unroll
    for (int r = 0; r < 8; r++) {
        int row = row0 + rg * 8 + r;
        *(float4*)&g_h[(size_t)row * OUT_F + (cg << 2)] =
            make_float4(acc[r][0], acc[r][1], acc[r][2], acc[r][3]);
    }
}

// ======================= Kernel B: p = h@a1, q = h@a2 =========================
__global__ void __launch_bounds__(256) pq_kernel(const float* __restrict__ a1,
                                                 const float* __restrict__ a2) {
    int gwarp = (blockIdx.x * blockDim.x + threadIdx.x) >> 5;
    int lane  = threadIdx.x & 31;
    if (gwarp >= N_NODES) return;
    float4 hv  = *(const float4*)&g_h[(size_t)gwarp * OUT_F + (lane << 2)];
    float4 av1 = *(const float4*)&a1[lane << 2];
    float4 av2 = *(const float4*)&a2[lane << 2];
    float s1 = hv.x * av1.x + hv.y * av1.y + hv.z * av1.z + hv.w * av1.w;
    float s2 = hv.x * av2.x + hv.y * av2.y + hv.z * av2.z + hv.w * av2.w;
#pragma unroll
    for (int o = 16; o; o >>= 1) {
        s1 += __shfl_xor_sync(0xffffffffu, s1, o);
        s2 += __shfl_xor_sync(0xffffffffu, s2, o);
    }
    if (lane == 0) { g_p[gwarp] = s1; g_q[gwarp] = s2; }
}

// ============ Kernel T: h -> h^T fp16 (transpose) =============================
__device__ __forceinline__ uint32_t pk2(__half a, __half b) {
    return (uint32_t)__half_as_ushort(a) | ((uint32_t)__half_as_ushort(b) << 16);
}
__global__ void __launch_bounds__(256) trans_kernel() {
    __shared__ float hs[32][132];
    const int tid = threadIdx.x;
    const int j0  = blockIdx.x * 32;
#pragma unroll
    for (int u = 0; u < 4; ++u) {
        int e = tid + u * 256;
        int r = e >> 5, c4 = (e & 31) << 2;
        *(float4*)&hs[r][c4] = *(const float4*)&g_h[(size_t)(j0 + r) * OUT_F + c4];
    }
    __syncthreads();
    const int f = tid >> 1, half = tid & 1;
    uint32_t hi8[8];
#pragma unroll
    for (int k = 0; k < 8; ++k) {
        float v0 = hs[half * 16 + 2 * k][f];
        float v1 = hs[half * 16 + 2 * k + 1][f];
        hi8[k] = pk2(__float2half_rn(v0), __float2half_rn(v1));
    }
    size_t ob = ((size_t)f * N_NODES + j0 + half * 16) * 2;
    *(uint4*)((char*)g_hT + ob)      = make_uint4(hi8[0], hi8[1], hi8[2], hi8[3]);
    *(uint4*)((char*)g_hT + ob + 16) = make_uint4(hi8[4], hi8[5], hi8[6], hi8[7]);
}

// ======================= Kernel C: cp.async-pipelined fused attention =========
// grid (64, SPLITJ), 384 thr. Warps 0-3 producers, 4-11 consumers.
// smem: A[2] w fp16 128x(144B) | B ring[3] h^T fp16 128x(144B) (cp.async dst)
//       | adj ring[3] 128x256B (cp.async dst) | bq[4096] f32 (exp(-q) table)
#define ABASE(b)  ((uint32_t)(b) * 18432u)
#define BBASE(s)  (36864u + (uint32_t)(s) * 18432u)
#define JBASE(s)  (92160u + (uint32_t)(s) * 32768u)
#define QBASE     190464u
#define SMEM_ATTN 206848u

// producers (tid 0..127): fire-and-forget stage of chunk cc into ring slot
#define ISSUE(cc) do {                                                           \
    const int slot_ = (cc) % 3;                                                  \
    const int j0_   = jstart + (cc) * 64;                                        \
    _Pragma("unroll")                                                            \
    for (int u = 0; u < 8; ++u) {                                                \
        int e = tid + u * 128;                                                   \
        int row = e >> 3, seg = e & 7;                                           \
        uint32_t dst = sb + BBASE(slot_) + (uint32_t)(row * 144 + seg * 16);     \
        const char* src = (const char*)g_hT + ((size_t)row * N_NODES + j0_) * 2  \
                          + seg * 16;                                            \
        CPA16(dst, src);                                                         \
    }                                                                            \
    _Pragma("unroll")                                                            \
    for (int u = 0; u < 16; ++u) {                                               \
        int e = tid + u * 128;                                                   \
        int row = e >> 4, seg = e & 15;                                          \
        uint32_t dst = sb + JBASE(slot_) + (uint32_t)(row * 256 + seg * 16);     \
        const char* src = (const char*)adj +                                     \
                          ((size_t)(i0 + row) * N_NODES + j0_) * 4 + seg * 16;   \
        CPA16(dst, src);                                                         \
    }                                                                            \
    CPA_COMMIT();                                                                \
} while (0)

// producers: weights of chunk cc from smem adj + bq table -> A[(cc)&1]
#define WEIGHT(cc) do {                                                          \
    const int slot_ = (cc) % 3;                                                  \
    const uint32_t ab_ = sb + ABASE((cc) & 1);                                   \
    float4 b0 = lds128f(sb + QBASE + (uint32_t)(((cc) * 64 + jo) * 4));          \
    float4 b1 = lds128f(sb + QBASE + (uint32_t)(((cc) * 64 + jo) * 4 + 16));     \
    const uint32_t jb_ = sb + JBASE(slot_) + (uint32_t)(rbase * 256 + jo * 4);   \
    _Pragma("unroll")                                                            \
    for (int u = 0; u < 8; ++u) {                                                \
        int4 m0 = lds128i(jb_ + u * 16 * 256);                                   \
        int4 m1 = lds128i(jb_ + u * 16 * 256 + 16);                              \
        float w0 = wpoly(a8[u], b0.x, m0.x), w1 = wpoly(a8[u], b0.y, m0.y);      \
        float w2 = wpoly(a8[u], b0.z, m0.z), w3 = wpoly(a8[u], b0.w, m0.w);      \
        float w4 = wpoly(a8[u], b1.x, m1.x), w5 = wpoly(a8[u], b1.y, m1.y);      \
        float w6 = wpoly(a8[u], b1.z, m1.z), w7 = wpoly(a8[u], b1.w, m1.w);      \
        dsum[u] += ((w0 + w1) + (w2 + w3)) + ((w4 + w5) + (w6 + w7));            \
        uint4 pw = make_uint4(pack_f16x2(w0, w1), pack_f16x2(w2, w3),            \
                              pack_f16x2(w4, w5), pack_f16x2(w6, w7));           \
        sts128(ab_ + (uint32_t)((rbase + 16 * u) * 144 + jo * 2), pw);           \
    }                                                                            \
} while (0)

__global__ void __launch_bounds__(384, 1) attn_kernel(const int* __restrict__ adj) {
    extern __shared__ __align__(16) char smem[];
    const uint32_t sb = smem_u32_of(smem);
    const int tid  = threadIdx.x;
    const int lane = tid & 31;
    const int wid  = tid >> 5;
    const int i0     = blockIdx.x * 128;
    const int jstart = blockIdx.y * (N_NODES / SPLITJ);

    // ---------- bq table: exp(-q_j) for this CTA's whole j range ----------
    for (int e = tid; e < N_NODES / SPLITJ; e += 384)
        stsf(sb + QBASE + (uint32_t)(e * 4), ex2f(-g_q[jstart + e] * LOG2E));

    // ---------- producer state (warps 0-3) ----------
    const int rbase = tid >> 3;          // 0..15
    const int jo    = (tid & 7) * 8;     // 0..56
    float a8[8], dsum[8];

    // ---------- consumer state (warps 4-11) ----------
    float acc[2][8][4];
    const int cw  = wid - 4;             // 0..7
    const int iw0 = (cw & 3) * 32;
    const int nw0 = (cw >> 2) * 64;
    const uint32_t aThb = (uint32_t)((iw0 + (lane & 15)) * 144 + 16 * (lane >> 4));
    const uint32_t bThb = (uint32_t)(((nw0 + (lane & 7) + 8 * ((lane >> 4) & 1)) * 144) +
                                     16 * ((lane >> 3) & 1));

    if (wid < 4) {
#pragma unroll
        for (int u = 0; u < 8; ++u) {
            a8[u]   = ex2f(-g_p[i0 + rbase + 16 * u] * LOG2E);
            dsum[u] = 0.f;
        }
        ISSUE(0);
        ISSUE(1);
        CPA_WAIT1();                     // chunk 0 resident
    } else {
#pragma unroll
        for (int mt = 0; mt < 2; ++mt)
#pragma unroll
            for (int nt = 0; nt < 8; ++nt)
#pragma unroll
                for (int k = 0; k < 4; ++k) acc[mt][nt][k] = 0.f;
    }
    __syncthreads();                     // bq + adj0/B0 visible to all
    if (wid < 4) WEIGHT(0);
    __syncthreads();                     // A0 ready

    for (int c = 0; c < NCHUNK; ++c) {
        if (wid < 4) {
            if (c + 2 < NCHUNK) { ISSUE(c + 2); CPA_WAIT1(); }
            else                { CPA_WAIT0(); }
            asm volatile("bar.sync 1, 128;" ::: "memory");   // producer-local
            if (c + 1 < NCHUNK) WEIGHT(c + 1);
        } else {
            const uint32_t ab = sb + ABASE(c & 1) + aThb;
            const uint32_t bb = sb + BBASE(c % 3) + bThb;
#pragma unroll
            for (int ks = 0; ks < 4; ++ks) {
                uint32_t A0[4], A1[4];
                LDSM4(A0, ab + ks * 32);
                LDSM4(A1, ab + 2304 + ks * 32);
#pragma unroll
                for (int nt2 = 0; nt2 < 4; ++nt2) {
                    uint32_t B[4];
                    LDSM4(B, bb + nt2 * 2304 + ks * 32);
                    MMA(acc[0][2 * nt2],     A0, B[0], B[1]);
                    MMA(acc[0][2 * nt2 + 1], A0, B[2], B[3]);
                    MMA(acc[1][2 * nt2],     A1, B[0], B[1]);
                    MMA(acc[1][2 * nt2 + 1], A1, B[2], B[3]);
                }
            }
        }
        __syncthreads();
    }

    if (wid < 4) {
        // denominators: 8 lanes (same row) hold partial sums over j
#pragma unroll
        for (int u = 0; u < 8; ++u) {
            float v = dsum[u];
            v += __shfl_xor_sync(0xffffffffu, v, 1);
            v += __shfl_xor_sync(0xffffffffu, v, 2);
            v += __shfl_xor_sync(0xffffffffu, v, 4);
            if ((lane & 7) == 0)
                g_den[blockIdx.y * N_NODES + i0 + rbase + 16 * u] = v;
        }
    } else {
        const int r0 = lane >> 2;
        const int cp = (lane & 3) * 2;
#pragma unroll
        for (int mt = 0; mt < 2; ++mt)
#pragma unroll
            for (int nt = 0; nt < 8; ++nt) {
                int row = i0 + iw0 + 16 * mt + r0;
                int col = nw0 + 8 * nt + cp;
                size_t base = ((size_t)blockIdx.y * N_NODES + row) * OUT_F + col;
                *(float2*)&g_acc[base] = make_float2(acc[mt][nt][0], acc[mt][nt][1]);
                *(float2*)&g_acc[base + 8 * OUT_F] =
                    make_float2(acc[mt][nt][2], acc[mt][nt][3]);
            }
    }
}

// ======================= Kernel D: combine splits =============================
__global__ void __launch_bounds__(256) combine_kernel(float* __restrict__ out) {
    int e = blockIdx.x * blockDim.x + threadIdx.x;
    int i = e >> 5;
    int c = (e & 31) << 2;
    float4 s = make_float4(0.f, 0.f, 0.f, 0.f);
    float d = 0.f;
#pragma unroll
    for (int sp = 0; sp < SPLITJ; sp++) {
        float4 a = *(const float4*)&g_acc[((size_t)sp * N_NODES + i) * OUT_F + c];
        s.x += a.x; s.y += a.y; s.z += a.z; s.w += a.w;
        d += g_den[sp * N_NODES + i];
    }
    float inv = __fdividef(1.f, d);
    *(float4*)&out[(size_t)i * OUT_F + c] =
        make_float4(s.x * inv, s.y * inv, s.z * inv, s.w * inv);
}

// =============================================================================
extern "C" void kernel_launch(void* const* d_in, const int* in_sizes, int n_in,
                              void* d_out, int out_size) {
    const float* X   = (const float*)d_in[0];
    const int*   adj = (const int*)d_in[1];
    const float* W   = (const float*)d_in[2];
    const float* a1  = (const float*)d_in[3];
    const float* a2  = (const float*)d_in[4];
    float* out = (float*)d_out;

    cudaFuncSetAttribute(attn_kernel, cudaFuncAttributeMaxDynamicSharedMemorySize,
                         SMEM_ATTN);

    gemm_xw_kernel<<<N_NODES / 64, 256>>>(X, W);
    pq_kernel<<<N_NODES / 8, 256>>>(a1, a2);
    trans_kernel<<<N_NODES / 32, 256>>>();
    attn_kernel<<<dim3(N_NODES / 128, SPLITJ), 384, SMEM_ATTN>>>(adj);
    combine_kernel<<<(N_NODES * 32) / 256, 256>>>(out);
}

// round 12
// speedup vs baseline: 1.6074x; 1.0609x over previous
#include <cuda_runtime.h>
#include <cuda_fp16.h>
#include <cstdint>

#define N_NODES 8192
#define IN_F    512
#define OUT_F   128
#define SPLITJ  2
#define NCHUNK  ((N_NODES / SPLITJ) / 64)   // 64
#define LOG2E   1.44269504f

// ---------------- scratch (device globals: no allocation allowed) -------------
__device__ float  g_h[(size_t)N_NODES * OUT_F];                // 4 MB
__device__ float  g_p[N_NODES];
__device__ float  g_q[N_NODES];
__device__ __half g_hT[(size_t)OUT_F * N_NODES];               // 2 MB  h^T fp16
__device__ float  g_acc[(size_t)SPLITJ * N_NODES * OUT_F];     // 8 MB
__device__ float  g_den[SPLITJ * N_NODES];

// ============================ helpers =========================================
__device__ __forceinline__ uint32_t smem_u32_of(const void* p) {
    uint32_t a;
    asm("{ .reg .u64 t; cvta.to.shared.u64 t, %1; cvt.u32.u64 %0, t; }"
        : "=r"(a) : "l"(p));
    return a;
}
__device__ __forceinline__ float ex2f(float x) {
    float r; asm("ex2.approx.f32 %0, %1;" : "=f"(r) : "f"(x)); return r;
}
__device__ __forceinline__ uint32_t pack_f16x2(float lo, float hi) {
    uint32_t r; asm("cvt.rn.f16x2.f32 %0, %1, %2;" : "=r"(r) : "f"(hi), "f"(lo));
    return r;
}
__device__ __forceinline__ void sts128(uint32_t a, uint4 v) {
    asm volatile("st.shared.v4.b32 [%0], {%1,%2,%3,%4};"
                 :: "r"(a), "r"(v.x), "r"(v.y), "r"(v.z), "r"(v.w));
}
__device__ __forceinline__ float4 lds128f(uint32_t a) {
    float4 v;
    asm volatile("ld.shared.v4.f32 {%0,%1,%2,%3}, [%4];"
                 : "=f"(v.x), "=f"(v.y), "=f"(v.z), "=f"(v.w) : "r"(a));
    return v;
}
__device__ __forceinline__ int4 lds128i(uint32_t a) {
    int4 v;
    asm volatile("ld.shared.v4.b32 {%0,%1,%2,%3}, [%4];"
                 : "=r"(v.x), "=r"(v.y), "=r"(v.z), "=r"(v.w) : "r"(a));
    return v;
}
__device__ __forceinline__ void stsf(uint32_t a, float v) {
    asm volatile("st.shared.f32 [%0], %1;" :: "r"(a), "f"(v));
}
#define CPA16(dst, src) \
    asm volatile("cp.async.cg.shared.global [%0], [%1], 16;" \
                 :: "r"(dst), "l"(src) : "memory")
#define CPA_COMMIT() asm volatile("cp.async.commit_group;" ::: "memory")
#define CPA_WAIT1()  asm volatile("cp.async.wait_group 1;" ::: "memory")
#define CPA_WAIT0()  asm volatile("cp.async.wait_group 0;" ::: "memory")

#define LDSM4(R, ADDR) \
    asm volatile("ldmatrix.sync.aligned.m8n8.x4.shared.b16 {%0,%1,%2,%3}, [%4];" \
                 : "=r"((R)[0]), "=r"((R)[1]), "=r"((R)[2]), "=r"((R)[3])        \
                 : "r"(ADDR))
#define MMA(C, A, B0, B1) \
    asm volatile("mma.sync.aligned.m16n8k16.row.col.f32.f16.f16.f32 "            \
                 "{%0,%1,%2,%3}, {%4,%5,%6,%7}, {%8,%9}, {%0,%1,%2,%3};"         \
                 : "+f"((C)[0]), "+f"((C)[1]), "+f"((C)[2]), "+f"((C)[3])        \
                 : "r"((A)[0]), "r"((A)[1]), "r"((A)[2]), "r"((A)[3]),           \
                   "r"(B0), "r"(B1))

// w = exp(sigmoid(p_i+q_j)) = exp(1/(1+a*b)); deg-4 poly for e^s on [0,1]
__device__ __forceinline__ float wpoly(float a, float b, int m) {
    float c = fmaf(a, b, 1.0f);
    float s; asm("rcp.approx.f32 %0, %1;" : "=f"(s) : "f"(c));
    float p = fmaf(0.069558f, s, 0.139972f);
    p = fmaf(p, s, 0.510039f);
    p = fmaf(p, s, 0.998663f);
    p = fmaf(p, s, 1.000035f);
    return (m != 0) ? p : 0.0f;
}

// ======================= Kernel A: h = X @ W (fp32) ===========================
__global__ void __launch_bounds__(256) gemm_xw_kernel(const float* __restrict__ X,
                                                      const float* __restrict__ W) {
    __shared__ float Xs[16][64];
    __shared__ float Ws[16][128];
    const int tid = threadIdx.x;
    const int rg  = tid >> 5;
    const int cg  = tid & 31;
    const int row0 = blockIdx.x * 64;

    float acc[8][4];
#pragma unroll
    for (int r = 0; r < 8; r++)
#pragma unroll
        for (int c = 0; c < 4; c++) acc[r][c] = 0.f;

    for (int k0 = 0; k0 < IN_F; k0 += 16) {
        {
            int r  = tid >> 2;
            int kq = (tid & 3) << 2;
            float4 v = *(const float4*)&X[(size_t)(row0 + r) * IN_F + k0 + kq];
            Xs[kq + 0][r] = v.x;  Xs[kq + 1][r] = v.y;
            Xs[kq + 2][r] = v.z;  Xs[kq + 3][r] = v.w;
        }
#pragma unroll
        for (int u = 0; u < 2; u++) {
            int e  = tid + u * 256;
            int kr = e >> 5;
            int cc = (e & 31) << 2;
            *(float4*)&Ws[kr][cc] = *(const float4*)&W[(size_t)(k0 + kr) * OUT_F + cc];
        }
        __syncthreads();
#pragma unroll
        for (int kk = 0; kk < 16; kk++) {
            float4 b = *(const float4*)&Ws[kk][cg << 2];
            float a8[8];
            *(float4*)&a8[0] = *(const float4*)&Xs[kk][rg * 8];
            *(float4*)&a8[4] = *(const float4*)&Xs[kk][rg * 8 + 4];
#pragma unroll
            for (int r = 0; r < 8; r++) {
                acc[r][0] += a8[r] * b.x;  acc[r][1] += a8[r] * b.y;
                acc[r][2] += a8[r] * b.z;  acc[r][3] += a8[r] * b.w;
            }
        }
        __syncthreads();
    }
#pragma unroll
    for (int r = 0; r < 8; r++) {
        int row = row0 + rg * 8 + r;
        *(float4*)&g_h[(size_t)row * OUT_F + (cg << 2)] =
            make_float4(acc[r][0], acc[r][1], acc[r][2], acc[r][3]);
    }
}

// ======================= Kernel B: p = h@a1, q = h@a2 =========================
__global__ void __launch_bounds__(256) pq_kernel(const float* __restrict__ a1,
                                                 const float* __restrict__ a2) {
    int gwarp = (blockIdx.x * blockDim.x + threadIdx.x) >> 5;
    int lane  = threadIdx.x & 31;
    if (gwarp >= N_NODES) return;
    float4 hv  = *(const float4*)&g_h[(size_t)gwarp * OUT_F + (lane << 2)];
    float4 av1 = *(const float4*)&a1[lane << 2];
    float4 av2 = *(const float4*)&a2[lane << 2];
    float s1 = hv.x * av1.x + hv.y * av1.y + hv.z * av1.z + hv.w * av1.w;
    float s2 = hv.x * av2.x + hv.y * av2.y + hv.z * av2.z + hv.w * av2.w;
#pragma unroll
    for (int o = 16; o; o >>= 1) {
        s1 += __shfl_xor_sync(0xffffffffu, s1, o);
        s2 += __shfl_xor_sync(0xffffffffu, s2, o);
    }
    if (lane == 0) { g_p[gwarp] = s1; g_q[gwarp] = s2; }
}

// ============ Kernel T: h -> h^T fp16 (transpose) =============================
__device__ __forceinline__ uint32_t pk2(__half a, __half b) {
    return (uint32_t)__half_as_ushort(a) | ((uint32_t)__half_as_ushort(b) << 16);
}
__global__ void __launch_bounds__(256) trans_kernel() {
    __shared__ float hs[32][132];
    const int tid = threadIdx.x;
    const int j0  = blockIdx.x * 32;
#pragma unroll
    for (int u = 0; u < 4; ++u) {
        int e = tid + u * 256;
        int r = e >> 5, c4 = (e & 31) << 2;
        *(float4*)&hs[r][c4] = *(const float4*)&g_h[(size_t)(j0 + r) * OUT_F + c4];
    }
    __syncthreads();
    const int f = tid >> 1, half = tid & 1;
    uint32_t hi8[8];
#pragma unroll
    for (int k = 0; k < 8; ++k) {
        float v0 = hs[half * 16 + 2 * k][f];
        float v1 = hs[half * 16 + 2 * k + 1][f];
        hi8[k] = pk2(__float2half_rn(v0), __float2half_rn(v1));
    }
    size_t ob = ((size_t)f * N_NODES + j0 + half * 16) * 2;
    *(uint4*)((char*)g_hT + ob)      = make_uint4(hi8[0], hi8[1], hi8[2], hi8[3]);
    *(uint4*)((char*)g_hT + ob + 16) = make_uint4(hi8[4], hi8[5], hi8[6], hi8[7]);
}

// ======================= Kernel C: cp.async-pipelined fused attention =========
// grid (64, SPLITJ), 768 thr. Warps 0-7 producers, 8-23 consumers (32x32 tiles).
// smem: A[2] w fp16 128x(144B) | B ring[3] h^T fp16 128x(144B) (cp.async dst)
//       | adj ring[3] 128x256B (cp.async dst) | bq[4096] f32 (exp(-q) table)
#define ABASE(b)  ((uint32_t)(b) * 18432u)
#define BBASE(s)  (36864u + (uint32_t)(s) * 18432u)
#define JBASE(s)  (92160u + (uint32_t)(s) * 32768u)
#define QBASE     190464u
#define SMEM_ATTN 206848u

// producers (tid 0..255): fire-and-forget stage of chunk cc into ring slot
#define ISSUE(cc) do {                                                           \
    const int slot_ = (cc) % 3;                                                  \
    const int j0_   = jstart + (cc) * 64;                                        \
    _Pragma("unroll")                                                            \
    for (int u = 0; u < 4; ++u) {                                                \
        int e = tid + u * 256;                                                   \
        int row = e >> 3, seg = e & 7;                                           \
        uint32_t dst = sb + BBASE(slot_) + (uint32_t)(row * 144 + seg * 16);     \
        const char* src = (const char*)g_hT + ((size_t)row * N_NODES + j0_) * 2  \
                          + seg * 16;                                            \
        CPA16(dst, src);                                                         \
    }                                                                            \
    _Pragma("unroll")                                                            \
    for (int u = 0; u < 8; ++u) {                                                \
        int e = tid + u * 256;                                                   \
        int row = e >> 4, seg = e & 15;                                          \
        uint32_t dst = sb + JBASE(slot_) + (uint32_t)(row * 256 + seg * 16);     \
        const char* src = (const char*)adj +                                     \
                          ((size_t)(i0 + row) * N_NODES + j0_) * 4 + seg * 16;   \
        CPA16(dst, src);                                                         \
    }                                                                            \
    CPA_COMMIT();                                                                \
} while (0)

// producers: weights of chunk cc from smem adj + bq table -> A[(cc)&1]
// thread covers rows rbase+32u (u<4), j = jo..jo+7
#define WEIGHT(cc) do {                                                          \
    const int slot_ = (cc) % 3;                                                  \
    const uint32_t ab_ = sb + ABASE((cc) & 1);                                   \
    float4 b0 = lds128f(sb + QBASE + (uint32_t)(((cc) * 64 + jo) * 4));          \
    float4 b1 = lds128f(sb + QBASE + (uint32_t)(((cc) * 64 + jo) * 4 + 16));     \
    const uint32_t jb_ = sb + JBASE(slot_) + (uint32_t)(rbase * 256 + jo * 4);   \
    _Pragma("unroll")                                                            \
    for (int u = 0; u < 4; ++u) {                                                \
        int4 m0 = lds128i(jb_ + u * 32 * 256);                                   \
        int4 m1 = lds128i(jb_ + u * 32 * 256 + 16);                              \
        float w0 = wpoly(a8[u], b0.x, m0.x), w1 = wpoly(a8[u], b0.y, m0.y);      \
        float w2 = wpoly(a8[u], b0.z, m0.z), w3 = wpoly(a8[u], b0.w, m0.w);      \
        float w4 = wpoly(a8[u], b1.x, m1.x), w5 = wpoly(a8[u], b1.y, m1.y);      \
        float w6 = wpoly(a8[u], b1.z, m1.z), w7 = wpoly(a8[u], b1.w, m1.w);      \
        dsum[u] += ((w0 + w1) + (w2 + w3)) + ((w4 + w5) + (w6 + w7));            \
        uint4 pw = make_uint4(pack_f16x2(w0, w1), pack_f16x2(w2, w3),            \
                              pack_f16x2(w4, w5), pack_f16x2(w6, w7));           \
        sts128(ab_ + (uint32_t)((rbase + 32 * u) * 144 + jo * 2), pw);           \
    }                                                                            \
} while (0)

__global__ void __launch_bounds__(768, 1) attn_kernel(const int* __restrict__ adj) {
    extern __shared__ __align__(16) char smem[];
    const uint32_t sb = smem_u32_of(smem);
    const int tid  = threadIdx.x;
    const int lane = tid & 31;
    const int wid  = tid >> 5;
    const int i0     = blockIdx.x * 128;
    const int jstart = blockIdx.y * (N_NODES / SPLITJ);

    // ---------- bq table: exp(-q_j) for this CTA's whole j range ----------
    for (int e = tid; e < N_NODES / SPLITJ; e += 768)
        stsf(sb + QBASE + (uint32_t)(e * 4), ex2f(-g_q[jstart + e] * LOG2E));

    // ---------- producer state (warps 0-7; tid 0..255) ----------
    const int rbase = tid >> 3;          // 0..31
    const int jo    = (tid & 7) * 8;     // 0..56
    float a8[4], dsum[4];

    // ---------- consumer state (warps 8-23): 32 i x 32 col each ----------
    float acc[2][4][4];
    const int cw  = wid - 8;             // 0..15
    const int iw0 = (cw & 3) * 32;
    const int nw0 = (cw >> 2) * 32;
    const uint32_t aThb = (uint32_t)((iw0 + (lane & 15)) * 144 + 16 * (lane >> 4));
    const uint32_t bThb = (uint32_t)(((nw0 + (lane & 7) + 8 * ((lane >> 4) & 1)) * 144) +
                                     16 * ((lane >> 3) & 1));

    if (wid < 8) {
#pragma unroll
        for (int u = 0; u < 4; ++u) {
            a8[u]   = ex2f(-g_p[i0 + rbase + 32 * u] * LOG2E);
            dsum[u] = 0.f;
        }
        ISSUE(0);
        ISSUE(1);
        CPA_WAIT1();                     // chunk 0 resident
    } else {
#pragma unroll
        for (int mt = 0; mt < 2; ++mt)
#pragma unroll
            for (int nt = 0; nt < 4; ++nt)
#pragma unroll
                for (int k = 0; k < 4; ++k) acc[mt][nt][k] = 0.f;
    }
    __syncthreads();                     // bq + adj0/B0 visible to all
    if (wid < 8) WEIGHT(0);
    __syncthreads();                     // A0 ready

    for (int c = 0; c < NCHUNK; ++c) {
        if (wid < 8) {
            if (c + 2 < NCHUNK) { ISSUE(c + 2); CPA_WAIT1(); }
            else                { CPA_WAIT0(); }
            asm volatile("bar.sync 1, 256;" ::: "memory");   // producer-local
            if (c + 1 < NCHUNK) WEIGHT(c + 1);
        } else {
            const uint32_t ab = sb + ABASE(c & 1) + aThb;
            const uint32_t bb = sb + BBASE(c % 3) + bThb;
#pragma unroll
            for (int ks = 0; ks < 4; ++ks) {
                uint32_t A0[4], A1[4];
                LDSM4(A0, ab + ks * 32);
                LDSM4(A1, ab + 2304 + ks * 32);
#pragma unroll
                for (int nt2 = 0; nt2 < 2; ++nt2) {
                    uint32_t B[4];
                    LDSM4(B, bb + nt2 * 2304 + ks * 32);
                    MMA(acc[0][2 * nt2],     A0, B[0], B[1]);
                    MMA(acc[0][2 * nt2 + 1], A0, B[2], B[3]);
                    MMA(acc[1][2 * nt2],     A1, B[0], B[1]);
                    MMA(acc[1][2 * nt2 + 1], A1, B[2], B[3]);
                }
            }
        }
        __syncthreads();
    }

    if (wid < 8) {
        // denominators: 8 lanes (same row) hold partial sums over j
#pragma unroll
        for (int u = 0; u < 4; ++u) {
            float v = dsum[u];
            v += __shfl_xor_sync(0xffffffffu, v, 1);
            v += __shfl_xor_sync(0xffffffffu, v, 2);
            v += __shfl_xor_sync(0xffffffffu, v, 4);
            if ((lane & 7) == 0)
                g_den[blockIdx.y * N_NODES + i0 + rbase + 32 * u] = v;
        }
    } else {
        const int r0 = lane >> 2;
        const int cp = (lane & 3) * 2;
#pragma unroll
        for (int mt = 0; mt < 2; ++mt)
#pragma unroll
            for (int nt = 0; nt < 4; ++nt) {
                int row = i0 + iw0 + 16 * mt + r0;
                int col = nw0 + 8 * nt + cp;
                size_t base = ((size_t)blockIdx.y * N_NODES + row) * OUT_F + col;
                *(float2*)&g_acc[base] = make_float2(acc[mt][nt][0], acc[mt][nt][1]);
                *(float2*)&g_acc[base + 8 * OUT_F] =
                    make_float2(acc[mt][nt][2], acc[mt][nt][3]);
            }
    }
}

// ======================= Kernel D: combine splits =============================
__global__ void __launch_bounds__(256) combine_kernel(float* __restrict__ out) {
    int e = blockIdx.x * blockDim.x + threadIdx.x;
    int i = e >> 5;
    int c = (e & 31) << 2;
    float4 s = make_float4(0.f, 0.f, 0.f, 0.f);
    float d = 0.f;
#pragma unroll
    for (int sp = 0; sp < SPLITJ; sp++) {
        float4 a = *(const float4*)&g_acc[((size_t)sp * N_NODES + i) * OUT_F + c];
        s.x += a.x; s.y += a.y; s.z += a.z; s.w += a.w;
        d += g_den[sp * N_NODES + i];
    }
    float inv = __fdividef(1.f, d);
    *(float4*)&out[(size_t)i * OUT_F + c] =
        make_float4(s.x * inv, s.y * inv, s.z * inv, s.w * inv);
}

// =============================================================================
extern "C" void kernel_launch(void* const* d_in, const int* in_sizes, int n_in,
                              void* d_out, int out_size) {
    const float* X   = (const float*)d_in[0];
    const int*   adj = (const int*)d_in[1];
    const float* W   = (const float*)d_in[2];
    const float* a1  = (const float*)d_in[3];
    const float* a2  = (const float*)d_in[4];
    float* out = (float*)d_out;

    cudaFuncSetAttribute(attn_kernel, cudaFuncAttributeMaxDynamicSharedMemorySize,
                         SMEM_ATTN);

    gemm_xw_kernel<<<N_NODES / 64, 256>>>(X, W);
    pq_kernel<<<N_NODES / 8, 256>>>(a1, a2);
    trans_kernel<<<N_NODES / 32, 256>>>();
    attn_kernel<<<dim3(N_NODES / 128, SPLITJ), 768, SMEM_ATTN>>>(adj);
    combine_kernel<<<(N_NODES * 32) / 256, 256>>>(out);
}